// round 6
// baseline (speedup 1.0000x reference)
#include <cuda_runtime.h>
#include <cstdint>

#define NN 100000
#define EE_MAX 3200000
#define DD 128

// Scratch (device globals; no allocation allowed; 16B aligned for float4)
__device__ __align__(16) float g_Z[NN * DD];   // transformed messages
__device__ __align__(16) float g_R[NN * DD];   // root path
__device__ __align__(16) float g_H[NN * DD];   // layer-1 output
__device__ int g_CNT[NN];                      // in-degree
__device__ int g_ROWPTR[NN];                   // CSR row starts
__device__ int g_CUR[NN];                      // fill cursors
__device__ int g_EIDX[EE_MAX];                 // CSR column (src) indices
__device__ int g_BSUM[128];                    // scan block sums
__device__ int g_IS64;                         // edge_index dtype flag

#define SCAN_BLK 1024
#define NBLK_SCAN ((NN + SCAN_BLK - 1) / SCAN_BLK)

// ---------------------------------------------------------------------------
// Edge-index dtype detection: int64 node ids are < NN; int32 pairs read as
// int64 have a random id in the high word -> value >= 2^32 almost surely.
// ---------------------------------------------------------------------------
__global__ void detect_kernel(const void* __restrict__ ei) {
    if (blockIdx.x == 0 && threadIdx.x == 0) {
        const long long* p = (const long long*)ei;
        int is64 = 1;
        for (int i = 0; i < 16; i++) {
            long long v = p[i];
            if (v < 0 || v >= (long long)NN) { is64 = 0; break; }
        }
        g_IS64 = is64;
    }
}

__device__ __forceinline__ int edge_at(const void* ei, int is64, int i) {
    if (is64) return (int)((const long long*)ei)[i];
    return ((const int*)ei)[i];
}

// ---------------------------------------------------------------------------
__global__ void zero_cnt_kernel() {
    int i = blockIdx.x * blockDim.x + threadIdx.x;
    if (i < NN) g_CNT[i] = 0;
}

// dst values live at element offsets [E, 2E)
__global__ void count_kernel(const void* __restrict__ ei, int E) {
    int i = blockIdx.x * blockDim.x + threadIdx.x;
    int stride = gridDim.x * blockDim.x;
    const int is64 = g_IS64;
    for (; i < E; i += stride) {
        int d = edge_at(ei, is64, E + i);
        if ((unsigned)d < (unsigned)NN) atomicAdd(&g_CNT[d], 1);
    }
}

// ---------------------------------------------------------------------------
// Exclusive scan of g_CNT -> g_ROWPTR, three phases.
// ---------------------------------------------------------------------------
__global__ __launch_bounds__(SCAN_BLK)
void scan1_kernel() {
    __shared__ int s[SCAN_BLK];
    int t = threadIdx.x;
    int gi = blockIdx.x * SCAN_BLK + t;
    int v = (gi < NN) ? g_CNT[gi] : 0;
    s[t] = v;
    __syncthreads();
    for (int off = 1; off < SCAN_BLK; off <<= 1) {
        int add = (t >= off) ? s[t - off] : 0;
        __syncthreads();
        s[t] += add;
        __syncthreads();
    }
    if (gi < NN) g_ROWPTR[gi] = s[t] - v;  // exclusive
    if (t == SCAN_BLK - 1) g_BSUM[blockIdx.x] = s[t];
}

__global__ void scan2_kernel() {
    if (threadIdx.x == 0) {
        int acc = 0;
        for (int b = 0; b < NBLK_SCAN; b++) {
            int v = g_BSUM[b];
            g_BSUM[b] = acc;
            acc += v;
        }
    }
}

__global__ void scan3_kernel() {
    int gi = blockIdx.x * blockDim.x + threadIdx.x;
    if (gi < NN) {
        int r = g_ROWPTR[gi] + g_BSUM[gi / SCAN_BLK];
        g_ROWPTR[gi] = r;
        g_CUR[gi] = r;
    }
}

// ---------------------------------------------------------------------------
// CSR fill: eidx[cursor[dst]++] = src
// ---------------------------------------------------------------------------
__global__ void fill_kernel(const void* __restrict__ ei, int E) {
    int i = blockIdx.x * blockDim.x + threadIdx.x;
    int stride = gridDim.x * blockDim.x;
    const int is64 = g_IS64;
    for (; i < E; i += stride) {
        int s = edge_at(ei, is64, i);
        int d = edge_at(ei, is64, E + i);
        if ((unsigned)d < (unsigned)NN && (unsigned)s < (unsigned)NN) {
            int pos = atomicAdd(&g_CUR[d], 1);
            if ((unsigned)pos < (unsigned)EE_MAX) g_EIDX[pos] = s;
        }
    }
}

// ---------------------------------------------------------------------------
// Dual GEMM: g_Z = A @ WL^T, g_R = A @ WR^T.  A:[N,128], W:[128,128] (out,in).
// UseH: A = g_H (device-global, resolved in device code).
// WPAD MUST be a multiple of 4: float4 loads at sW[k*WPAD + o4] need 16B
// alignment (LDS.128 traps otherwise).
// ---------------------------------------------------------------------------
#define KC 32
#define WPAD 132
#define APAD 33

template <bool UseH>
__global__ __launch_bounds__(256)
void gemm_dual(const float* __restrict__ Aext,
               const float* __restrict__ WL, const float* __restrict__ WR,
               int N) {
    __shared__ float sWL[KC * WPAD];
    __shared__ float sWR[KC * WPAD];
    __shared__ float sA[64 * APAD];

    const float* A = UseH ? (const float*)g_H : Aext;

    const int t = threadIdx.x;
    const int n0 = blockIdx.x * 64;
    const int o4 = (t & 31) * 4;
    const int gg = t >> 5;

    float accL[8][4], accR[8][4];
#pragma unroll
    for (int i = 0; i < 8; i++)
#pragma unroll
        for (int j = 0; j < 4; j++) { accL[i][j] = 0.0f; accR[i][j] = 0.0f; }

    for (int kc = 0; kc < 128; kc += KC) {
        if (kc) __syncthreads();
        for (int idx = t; idx < KC * 128; idx += 256) {
            int k = idx & 31;
            int o = idx >> 5;
            sWL[k * WPAD + o] = WL[o * 128 + kc + k];
            sWR[k * WPAD + o] = WR[o * 128 + kc + k];
        }
        for (int idx = t; idx < 64 * KC; idx += 256) {
            int k = idx & 31;
            int n = idx >> 5;
            int row = n0 + n;
            sA[n * APAD + k] = (row < N) ? A[(size_t)row * 128 + kc + k] : 0.0f;
        }
        __syncthreads();

#pragma unroll 4
        for (int k = 0; k < KC; k++) {
            float4 wl = *(const float4*)&sWL[k * WPAD + o4];
            float4 wr = *(const float4*)&sWR[k * WPAD + o4];
#pragma unroll
            for (int i = 0; i < 8; i++) {
                float a = sA[(gg * 8 + i) * APAD + k];
                accL[i][0] += a * wl.x; accL[i][1] += a * wl.y;
                accL[i][2] += a * wl.z; accL[i][3] += a * wl.w;
                accR[i][0] += a * wr.x; accR[i][1] += a * wr.y;
                accR[i][2] += a * wr.z; accR[i][3] += a * wr.w;
            }
        }
    }

#pragma unroll
    for (int i = 0; i < 8; i++) {
        int row = n0 + gg * 8 + i;
        if (row < N) {
            *(float4*)&g_Z[(size_t)row * 128 + o4] =
                make_float4(accL[i][0], accL[i][1], accL[i][2], accL[i][3]);
            *(float4*)&g_R[(size_t)row * 128 + o4] =
                make_float4(accR[i][0], accR[i][1], accR[i][2], accR[i][3]);
        }
    }
}

// ---------------------------------------------------------------------------
// Fused aggregate + node update. One warp per node.
// h = relu(mean_{s in row} Z[s] + bl + R[n])
// MODE 0: write H row.  MODE 1: out[n] = h . Wc + bc  (classifier fused).
// ---------------------------------------------------------------------------
template <int MODE>
__global__ __launch_bounds__(256)
void sage_agg(const float* __restrict__ bl,
              const float* __restrict__ Wc,
              const float* __restrict__ bc,
              float* __restrict__ out, int N) {
    int warp = (blockIdx.x * blockDim.x + threadIdx.x) >> 5;
    int lane = threadIdx.x & 31;
    if (warp >= N) return;

    const int base = g_ROWPTR[warp];
    const int len = g_CNT[warp];
    const int o4 = lane * 4;

    float4 acc = make_float4(0.f, 0.f, 0.f, 0.f);
    for (int j0 = 0; j0 < len; j0 += 32) {
        int rem = len - j0;
        int m = (rem < 32) ? rem : 32;
        int myidx = (lane < m) ? g_EIDX[base + j0 + lane] : 0;
        for (int t = 0; t < m; t++) {
            int s = __shfl_sync(0xFFFFFFFFu, myidx, t);
            float4 v = *(const float4*)(g_Z + (size_t)s * 128 + o4);
            acc.x += v.x; acc.y += v.y; acc.z += v.z; acc.w += v.w;
        }
    }

    float inv = 1.0f / fmaxf((float)len, 1.0f);
    float4 r = *(const float4*)(g_R + (size_t)warp * 128 + o4);
    float4 b = *(const float4*)&bl[o4];
    float4 h;
    h.x = fmaxf(fmaf(acc.x, inv, b.x + r.x), 0.0f);
    h.y = fmaxf(fmaf(acc.y, inv, b.y + r.y), 0.0f);
    h.z = fmaxf(fmaf(acc.z, inv, b.z + r.z), 0.0f);
    h.w = fmaxf(fmaf(acc.w, inv, b.w + r.w), 0.0f);

    if (MODE == 0) {
        *(float4*)(g_H + (size_t)warp * 128 + o4) = h;
    } else {
        float4 wc = *(const float4*)&Wc[o4];
        float s = h.x * wc.x + h.y * wc.y + h.z * wc.z + h.w * wc.w;
#pragma unroll
        for (int off = 16; off; off >>= 1)
            s += __shfl_down_sync(0xFFFFFFFFu, s, off);
        if (lane == 0) out[warp] = s + bc[0];
    }
}

// ---------------------------------------------------------------------------
extern "C" void kernel_launch(void* const* d_in, const int* in_sizes, int n_in,
                              void* d_out, int out_size) {
    const float* x   = (const float*)d_in[0];
    const void* ei   = d_in[1];
    const float* Wl1 = (const float*)d_in[2];
    const float* bl1 = (const float*)d_in[3];
    const float* Wr1 = (const float*)d_in[4];
    const float* Wl2 = (const float*)d_in[5];
    const float* bl2 = (const float*)d_in[6];
    const float* Wr2 = (const float*)d_in[7];
    const float* Wc  = (const float*)d_in[8];
    const float* bc  = (const float*)d_in[9];
    float* out       = (float*)d_out;

    const int N = in_sizes[0] / DD;
    const int E = in_sizes[1] / 2;

    const int gemm_blocks = (N + 63) / 64;
    const int agg_blocks = (N + 7) / 8;   // 8 warps per block

    // ---- CSR build ----
    detect_kernel<<<1, 32>>>(ei);
    zero_cnt_kernel<<<(NN + 255) / 256, 256>>>();
    count_kernel<<<2048, 256>>>(ei, E);
    scan1_kernel<<<NBLK_SCAN, SCAN_BLK>>>();
    scan2_kernel<<<1, 32>>>();
    scan3_kernel<<<(NN + 255) / 256, 256>>>();
    fill_kernel<<<2048, 256>>>(ei, E);

    // ---- Layer 1 ----
    gemm_dual<false><<<gemm_blocks, 256>>>(x, Wl1, Wr1, N);
    sage_agg<0><<<agg_blocks, 256>>>(bl1, nullptr, nullptr, nullptr, N);

    // ---- Layer 2 + classifier ----
    gemm_dual<true><<<gemm_blocks, 256>>>(nullptr, Wl2, Wr2, N);
    sage_agg<1><<<agg_blocks, 256>>>(bl2, Wc, bc, out, N);
}

// round 8
// speedup vs baseline: 1.0996x; 1.0996x over previous
#include <cuda_runtime.h>
#include <cstdint>

#define NN 100000
#define EE_MAX 3200000
#define DD 128

typedef unsigned long long ull;

// Scratch (device globals; no allocation allowed; 16B aligned for float4)
__device__ __align__(16) float g_Z[NN * DD];   // transformed messages
__device__ __align__(16) float g_R[NN * DD];   // root path
__device__ __align__(16) float g_H[NN * DD];   // layer-1 output
__device__ int g_CNT[NN];                      // in-degree
__device__ int g_ROWPTR[NN];                   // CSR row starts
__device__ int g_CUR[NN];                      // fill cursors
__device__ int g_EIDX[EE_MAX];                 // CSR column (src) indices
__device__ int g_BSUM[128];                    // scan block sums
__device__ int g_IS64;                         // edge_index dtype flag

#define SCAN_BLK 1024
#define NBLK_SCAN ((NN + SCAN_BLK - 1) / SCAN_BLK)

// ---------------------------------------------------------------------------
// f32x2 packed-FMA helpers (sm_103a FFMA2; exact fp32, 2 FMAs per issue)
// ---------------------------------------------------------------------------
__device__ __forceinline__ ull dup2(float x) {
    ull r;
    asm("mov.b64 %0, {%1, %1};" : "=l"(r) : "f"(x));
    return r;
}
__device__ __forceinline__ void fma2(ull& d, ull a, ull b) {
    asm("fma.rn.f32x2 %0, %1, %2, %0;" : "+l"(d) : "l"(a), "l"(b));
}
__device__ __forceinline__ void unpk(float& lo, float& hi, ull v) {
    asm("mov.b64 {%0, %1}, %2;" : "=f"(lo), "=f"(hi) : "l"(v));
}

// ---------------------------------------------------------------------------
// Edge-index dtype detection: int64 node ids are < NN; int32 pairs read as
// int64 have a random id in the high word -> value >= 2^32 almost surely.
// ---------------------------------------------------------------------------
__global__ void detect_kernel(const void* __restrict__ ei) {
    if (blockIdx.x == 0 && threadIdx.x == 0) {
        const long long* p = (const long long*)ei;
        int is64 = 1;
        for (int i = 0; i < 16; i++) {
            long long v = p[i];
            if (v < 0 || v >= (long long)NN) { is64 = 0; break; }
        }
        g_IS64 = is64;
    }
}

__device__ __forceinline__ int edge_at(const void* ei, int is64, int i) {
    if (is64) return (int)((const long long*)ei)[i];
    return ((const int*)ei)[i];
}

// ---------------------------------------------------------------------------
__global__ void zero_cnt_kernel() {
    int i = blockIdx.x * blockDim.x + threadIdx.x;
    if (i < NN) g_CNT[i] = 0;
}

// dst values live at element offsets [E, 2E)
__global__ void count_kernel(const void* __restrict__ ei, int E) {
    int i = blockIdx.x * blockDim.x + threadIdx.x;
    int stride = gridDim.x * blockDim.x;
    const int is64 = g_IS64;
    for (; i < E; i += stride) {
        int d = edge_at(ei, is64, E + i);
        if ((unsigned)d < (unsigned)NN) atomicAdd(&g_CNT[d], 1);
    }
}

// ---------------------------------------------------------------------------
// Exclusive scan of g_CNT -> g_ROWPTR, three phases.
// ---------------------------------------------------------------------------
__global__ __launch_bounds__(SCAN_BLK)
void scan1_kernel() {
    __shared__ int s[SCAN_BLK];
    int t = threadIdx.x;
    int gi = blockIdx.x * SCAN_BLK + t;
    int v = (gi < NN) ? g_CNT[gi] : 0;
    s[t] = v;
    __syncthreads();
    for (int off = 1; off < SCAN_BLK; off <<= 1) {
        int add = (t >= off) ? s[t - off] : 0;
        __syncthreads();
        s[t] += add;
        __syncthreads();
    }
    if (gi < NN) g_ROWPTR[gi] = s[t] - v;  // exclusive
    if (t == SCAN_BLK - 1) g_BSUM[blockIdx.x] = s[t];
}

__global__ void scan2_kernel() {
    if (threadIdx.x == 0) {
        int acc = 0;
        for (int b = 0; b < NBLK_SCAN; b++) {
            int v = g_BSUM[b];
            g_BSUM[b] = acc;
            acc += v;
        }
    }
}

__global__ void scan3_kernel() {
    int gi = blockIdx.x * blockDim.x + threadIdx.x;
    if (gi < NN) {
        int r = g_ROWPTR[gi] + g_BSUM[gi / SCAN_BLK];
        g_ROWPTR[gi] = r;
        g_CUR[gi] = r;
    }
}

// ---------------------------------------------------------------------------
// CSR fill: eidx[cursor[dst]++] = src
// ---------------------------------------------------------------------------
__global__ void fill_kernel(const void* __restrict__ ei, int E) {
    int i = blockIdx.x * blockDim.x + threadIdx.x;
    int stride = gridDim.x * blockDim.x;
    const int is64 = g_IS64;
    for (; i < E; i += stride) {
        int s = edge_at(ei, is64, i);
        int d = edge_at(ei, is64, E + i);
        if ((unsigned)d < (unsigned)NN && (unsigned)s < (unsigned)NN) {
            int pos = atomicAdd(&g_CUR[d], 1);
            if ((unsigned)pos < (unsigned)EE_MAX) g_EIDX[pos] = s;
        }
    }
}

// ---------------------------------------------------------------------------
// Dual GEMM via packed FFMA2: g_Z = A @ WL^T, g_R = A @ WR^T.
// A:[N,128], W:[128,128] (out,in). UseH: A = g_H.
// Accumulators pack adjacent NODES: acc[pair][out] = (node 2p, node 2p+1).
// sA stored transposed [k][n] (NPAD even -> aligned LDS.64; warp-uniform
// address -> smem broadcast). Weight scalars dup-packed (w,w) per k.
// WPAD multiple of 4 (float4 LDS.128 alignment).
// ---------------------------------------------------------------------------
#define KC 32
#define WPAD 132
#define NPAD 66

template <bool UseH>
__global__ __launch_bounds__(256)
void gemm_dual(const float* __restrict__ Aext,
               const float* __restrict__ WL, const float* __restrict__ WR,
               int N) {
    __shared__ float sWL[KC * WPAD];
    __shared__ float sWR[KC * WPAD];
    __shared__ float sA[KC * NPAD];   // [k][n]

    const float* A = UseH ? (const float*)g_H : Aext;

    const int t = threadIdx.x;
    const int n0 = blockIdx.x * 64;
    const int o4 = (t & 31) * 4;   // 4 consecutive output cols
    const int gg = t >> 5;         // node group: 8 nodes (4 pairs)

    ull accL[4][4], accR[4][4];    // [node pair][output col]
#pragma unroll
    for (int p = 0; p < 4; p++)
#pragma unroll
        for (int j = 0; j < 4; j++) { accL[p][j] = 0ULL; accR[p][j] = 0ULL; }

    for (int kc = 0; kc < 128; kc += KC) {
        if (kc) __syncthreads();
        // Weights transposed: sW[k*WPAD + o] = W[o*128 + kc + k]
        for (int idx = t; idx < KC * 128; idx += 256) {
            int k = idx & 31;
            int o = idx >> 5;
            sWL[k * WPAD + o] = WL[o * 128 + kc + k];
            sWR[k * WPAD + o] = WR[o * 128 + kc + k];
        }
        // A transposed into [k][n]: sA[k*NPAD + n] = A[(n0+n)*128 + kc + k]
        for (int idx = t; idx < 64 * KC; idx += 256) {
            int k = idx & 31;   // lane -> coalesced global read
            int n = idx >> 5;
            int row = n0 + n;
            sA[k * NPAD + n] = (row < N) ? A[(size_t)row * 128 + kc + k] : 0.0f;
        }
        __syncthreads();

#pragma unroll 2
        for (int k = 0; k < KC; k++) {
            float4 wl = *(const float4*)&sWL[k * WPAD + o4];
            float4 wr = *(const float4*)&sWR[k * WPAD + o4];
            ull wlp[4] = { dup2(wl.x), dup2(wl.y), dup2(wl.z), dup2(wl.w) };
            ull wrp[4] = { dup2(wr.x), dup2(wr.y), dup2(wr.z), dup2(wr.w) };
            const ull* ap = (const ull*)&sA[k * NPAD + gg * 8];  // broadcast
#pragma unroll
            for (int p = 0; p < 4; p++) {
                ull a2 = ap[p];   // (a[2p], a[2p+1])
                fma2(accL[p][0], a2, wlp[0]);
                fma2(accL[p][1], a2, wlp[1]);
                fma2(accL[p][2], a2, wlp[2]);
                fma2(accL[p][3], a2, wlp[3]);
                fma2(accR[p][0], a2, wrp[0]);
                fma2(accR[p][1], a2, wrp[1]);
                fma2(accR[p][2], a2, wrp[2]);
                fma2(accR[p][3], a2, wrp[3]);
            }
        }
    }

#pragma unroll
    for (int p = 0; p < 4; p++) {
        int r0 = n0 + gg * 8 + 2 * p;
        int r1 = r0 + 1;
        float zl0[4], zl1[4], zr0[4], zr1[4];
#pragma unroll
        for (int j = 0; j < 4; j++) {
            unpk(zl0[j], zl1[j], accL[p][j]);
            unpk(zr0[j], zr1[j], accR[p][j]);
        }
        if (r0 < N) {
            *(float4*)&g_Z[(size_t)r0 * 128 + o4] =
                make_float4(zl0[0], zl0[1], zl0[2], zl0[3]);
            *(float4*)&g_R[(size_t)r0 * 128 + o4] =
                make_float4(zr0[0], zr0[1], zr0[2], zr0[3]);
        }
        if (r1 < N) {
            *(float4*)&g_Z[(size_t)r1 * 128 + o4] =
                make_float4(zl1[0], zl1[1], zl1[2], zl1[3]);
            *(float4*)&g_R[(size_t)r1 * 128 + o4] =
                make_float4(zr1[0], zr1[1], zr1[2], zr1[3]);
        }
    }
}

// ---------------------------------------------------------------------------
// Fused aggregate + node update. One warp per node.
// h = relu(mean_{s in row} Z[s] + bl + R[n])
// MODE 0: write H row.  MODE 1: out[n] = h . Wc + bc  (classifier fused).
// ---------------------------------------------------------------------------
template <int MODE>
__global__ __launch_bounds__(256)
void sage_agg(const float* __restrict__ bl,
              const float* __restrict__ Wc,
              const float* __restrict__ bc,
              float* __restrict__ out, int N) {
    int warp = (blockIdx.x * blockDim.x + threadIdx.x) >> 5;
    int lane = threadIdx.x & 31;
    if (warp >= N) return;

    const int base = g_ROWPTR[warp];
    const int len = g_CNT[warp];
    const int o4 = lane * 4;

    float4 acc = make_float4(0.f, 0.f, 0.f, 0.f);
    for (int j0 = 0; j0 < len; j0 += 32) {
        int rem = len - j0;
        int m = (rem < 32) ? rem : 32;
        int myidx = (lane < m) ? g_EIDX[base + j0 + lane] : 0;
        for (int t = 0; t < m; t++) {
            int s = __shfl_sync(0xFFFFFFFFu, myidx, t);
            float4 v = *(const float4*)(g_Z + (size_t)s * 128 + o4);
            acc.x += v.x; acc.y += v.y; acc.z += v.z; acc.w += v.w;
        }
    }

    float inv = 1.0f / fmaxf((float)len, 1.0f);
    float4 r = *(const float4*)(g_R + (size_t)warp * 128 + o4);
    float4 b = *(const float4*)&bl[o4];
    float4 h;
    h.x = fmaxf(fmaf(acc.x, inv, b.x + r.x), 0.0f);
    h.y = fmaxf(fmaf(acc.y, inv, b.y + r.y), 0.0f);
    h.z = fmaxf(fmaf(acc.z, inv, b.z + r.z), 0.0f);
    h.w = fmaxf(fmaf(acc.w, inv, b.w + r.w), 0.0f);

    if (MODE == 0) {
        *(float4*)(g_H + (size_t)warp * 128 + o4) = h;
    } else {
        float4 wc = *(const float4*)&Wc[o4];
        float s = h.x * wc.x + h.y * wc.y + h.z * wc.z + h.w * wc.w;
#pragma unroll
        for (int off = 16; off; off >>= 1)
            s += __shfl_down_sync(0xFFFFFFFFu, s, off);
        if (lane == 0) out[warp] = s + bc[0];
    }
}

// ---------------------------------------------------------------------------
extern "C" void kernel_launch(void* const* d_in, const int* in_sizes, int n_in,
                              void* d_out, int out_size) {
    const float* x   = (const float*)d_in[0];
    const void* ei   = d_in[1];
    const float* Wl1 = (const float*)d_in[2];
    const float* bl1 = (const float*)d_in[3];
    const float* Wr1 = (const float*)d_in[4];
    const float* Wl2 = (const float*)d_in[5];
    const float* bl2 = (const float*)d_in[6];
    const float* Wr2 = (const float*)d_in[7];
    const float* Wc  = (const float*)d_in[8];
    const float* bc  = (const float*)d_in[9];
    float* out       = (float*)d_out;

    const int N = in_sizes[0] / DD;
    const int E = in_sizes[1] / 2;

    const int gemm_blocks = (N + 63) / 64;
    const int agg_blocks = (N + 7) / 8;   // 8 warps per block

    // ---- CSR build ----
    detect_kernel<<<1, 32>>>(ei);
    zero_cnt_kernel<<<(NN + 255) / 256, 256>>>();
    count_kernel<<<2048, 256>>>(ei, E);
    scan1_kernel<<<NBLK_SCAN, SCAN_BLK>>>();
    scan2_kernel<<<1, 32>>>();
    scan3_kernel<<<(NN + 255) / 256, 256>>>();
    fill_kernel<<<2048, 256>>>(ei, E);

    // ---- Layer 1 ----
    gemm_dual<false><<<gemm_blocks, 256>>>(x, Wl1, Wr1, N);
    sage_agg<0><<<agg_blocks, 256>>>(bl1, nullptr, nullptr, nullptr, N);

    // ---- Layer 2 + classifier ----
    gemm_dual<true><<<gemm_blocks, 256>>>(nullptr, Wl2, Wr2, N);
    sage_agg<1><<<agg_blocks, 256>>>(bl2, Wc, bc, out, N);
}